// round 6
// baseline (speedup 1.0000x reference)
#include <cuda_runtime.h>
#include <math.h>

#define PI_F 3.14159265358979323846f
#define N_NODES 4096
#define N_EDGES 12288
#define NUM_GRAPHS 16
#define PQC_BLOCKS 512

typedef unsigned long long ull;

// ---------------- device scratch ----------------
__device__ float  g_x[N_NODES * 2];     // node angles (update-MLP input & segment sum)
__device__ float4 g_x4[N_NODES];        // node wire amplitudes
__device__ float4 g_e4[N_EDGES];        // edge wire amplitudes
__device__ ull    g_gx[112];            // 14 gate matrices, splatted-packed (8 ull each)
__device__ ull    g_wx[128];            // 4 iter0 columns x 16 amps x (W, iW)
__device__ float  g_gsum[NUM_GRAPHS * 2];
__device__ float  g_gcnt[NUM_GRAPHS];
__device__ int    g_done;

// ---------------- packed f32x2 helpers ----------------
__device__ __forceinline__ ull pk(float x, float y) {
    ull r; asm("mov.b64 %0,{%1,%2};" : "=l"(r) : "f"(x), "f"(y)); return r;
}
__device__ __forceinline__ void upk(ull a, float& x, float& y) {
    asm("mov.b64 {%0,%1},%2;" : "=f"(x), "=f"(y) : "l"(a));
}
__device__ __forceinline__ ull fma2(ull a, ull b, ull c) {
    ull r; asm("fma.rn.f32x2 %0,%1,%2,%3;" : "=l"(r) : "l"(a), "l"(b), "l"(c)); return r;
}
__device__ __forceinline__ ull mul2(ull a, ull b) {
    ull r; asm("mul.rn.f32x2 %0,%1,%2;" : "=l"(r) : "l"(a), "l"(b)); return r;
}
__device__ __forceinline__ ull jsw(ull a) {   // i * (x + iy) = (-y, x)
    float x, y; upk(a, x, y); return pk(-y, x);
}

// ---------------- complex (scalar) helpers ----------------
__device__ __forceinline__ float2 cmul(float2 a, float2 b) {
    return make_float2(fmaf(a.x, b.x, -(a.y * b.y)), fmaf(a.x, b.y, a.y * b.x));
}
__device__ __forceinline__ float2 cadd(float2 a, float2 b) {
    return make_float2(a.x + b.x, a.y + b.y);
}

// ================= packed gate primitives =================
// U8 layout per 2x2 matrix [m0 m1; m2 m3]:
//   [0]=(m0.x,m0.x) [1]=(m0.y,m0.y) [2]=(m1.x,m1.x) [3]=(m1.y,m1.y)
//   [4]=(m2.x,..)   [5]=(m2.y,..)   [6]=(m3.x,..)   [7]=(m3.y,..)
// out_a = m0*a + m1*b ;  out_b = m2*a + m3*b  with u*a = u.x*a + u.y*(i a)
__device__ __forceinline__ void ap_pair(ull& A, ull& B, const ull* U8) {
    ull JA = jsw(A), JB = jsw(B);
    ull na = fma2(U8[0], A, fma2(U8[1], JA, fma2(U8[2], B, mul2(U8[3], JB))));
    ull nb = fma2(U8[4], A, fma2(U8[5], JA, fma2(U8[6], B, mul2(U8[7], JB))));
    A = na; B = nb;
}
// 1q gate on register bit J, single matrix
template <int J>
__device__ __forceinline__ void ap_reg2(ull* v, const ull* U8) {
#pragma unroll
    for (int r = 0; r < 16; r++) {
        if ((r >> J) & 1) continue;
        ap_pair(v[r], v[r | (1 << J)], U8);
    }
}
// 1q gate on register bit J with branch matrix selected by bits (3,2)
template <int J>
__device__ __forceinline__ void ap_branch(ull* v, const ull* FB) {
#pragma unroll
    for (int r = 0; r < 16; r++) {
        if ((r >> J) & 1) continue;
        ap_pair(v[r], v[r | (1 << J)], FB + 8 * ((r >> 2) & 3));
    }
}
// CNOT reg->reg: register renames (free)
template <int C, int T>
__device__ __forceinline__ void cnot_rr(ull* v) {
#pragma unroll
    for (int r = 0; r < 16; r++) {
        if (!((r >> C) & 1) || ((r >> T) & 1)) continue;
        int r2 = r | (1 << T);
        ull t = v[r]; v[r] = v[r2]; v[r2] = t;
    }
}
// swap register bit J with lane bit (mask)
template <int J>
__device__ __forceinline__ void swap_reg_lane(ull* v, int lane, int mask) {
    bool b = lane & mask;
#pragma unroll
    for (int r = 0; r < 16; r++) {
        if ((r >> J) & 1) continue;
        int r2 = r | (1 << J);
        ull send = b ? v[r] : v[r2];
        ull recv = __shfl_xor_sync(0xffffffffu, send, mask);
        if (b) v[r] = recv; else v[r2] = recv;
    }
}

// one ctrl+sel+sel iteration; G = base of 14-matrix table
__device__ __forceinline__ void iter_regs2(ull* v, const ull* G) {
    ap_branch<1>(v, G);          // FB1: R_a1 * CRY(e->a1) * CRX(nb->a1)
    ap_branch<0>(v, G + 32);     // FB0: R_a2 * CRY(e->a2) * CRZ(nb->a2)
    ap_reg2<3>(v, G + 64);       // R_e
    ap_reg2<2>(v, G + 72);       // R_nb
    cnot_rr<3, 2>(v);
    cnot_rr<2, 1>(v);
    cnot_rr<1, 3>(v);
    ap_reg2<1>(v, G + 80);       // R_a1'
    ap_reg2<2>(v, G + 88);       // R_nb'
    cnot_rr<1, 2>(v);
    cnot_rr<2, 0>(v);
    cnot_rr<0, 1>(v);
}

// ---------------- gate precompute ----------------
__device__ void make_rot(const float* w, float2* m) {
    float phi = w[0], th = w[1], om = w[2];
    float c, s; sincosf(th * 0.5f, &s, &c);
    float sa, ca, sb, cb;
    sincosf((phi + om) * 0.5f, &sa, &ca);
    sincosf((phi - om) * 0.5f, &sb, &cb);
    m[0] = make_float2(c * ca, -c * sa);
    m[1] = make_float2(-s * cb, -s * sb);
    m[2] = make_float2(s * cb, -s * sb);
    m[3] = make_float2(c * ca, c * sa);
}
__device__ void cm2(const float2* A, const float2* B, float2* C) {
    C[0] = cadd(cmul(A[0], B[0]), cmul(A[1], B[2]));
    C[1] = cadd(cmul(A[0], B[1]), cmul(A[1], B[3]));
    C[2] = cadd(cmul(A[2], B[0]), cmul(A[3], B[2]));
    C[3] = cadd(cmul(A[2], B[1]), cmul(A[3], B[3]));
}
__device__ void write_mat(int mi, const float2* m) {
    for (int k = 0; k < 4; k++) {
        g_gx[mi * 8 + 2 * k]     = pk(m[k].x, m[k].x);
        g_gx[mi * 8 + 2 * k + 1] = pk(m[k].y, m[k].y);
    }
}

__device__ void prep_gates(const float* strong, const float* inits, const float* update) {
    float c, s;
    float2 RX0[4], RY1[4], RZ2[4], RY3[4], I2[4];
    I2[0] = make_float2(1, 0); I2[1] = make_float2(0, 0);
    I2[2] = make_float2(0, 0); I2[3] = make_float2(1, 0);
    sincosf(inits[0] * 0.5f, &s, &c);
    RX0[0] = make_float2(c, 0); RX0[1] = make_float2(0, -s);
    RX0[2] = make_float2(0, -s); RX0[3] = make_float2(c, 0);
    sincosf(inits[1] * 0.5f, &s, &c);
    RY1[0] = make_float2(c, 0); RY1[1] = make_float2(-s, 0);
    RY1[2] = make_float2(s, 0); RY1[3] = make_float2(c, 0);
    sincosf(inits[2] * 0.5f, &s, &c);
    RZ2[0] = make_float2(c, -s); RZ2[1] = make_float2(0, 0);
    RZ2[2] = make_float2(0, 0);  RZ2[3] = make_float2(c, s);
    sincosf(inits[3] * 0.5f, &s, &c);
    RY3[0] = make_float2(c, 0); RY3[1] = make_float2(-s, 0);
    RY3[2] = make_float2(s, 0); RY3[3] = make_float2(c, 0);

    float2 Re[4], Rnb[4], Ra1[4], Ra1p[4], Rnbp[4], Ra2[4], U0[4], U1[4];
    make_rot(strong + 0,  Re);
    make_rot(strong + 3,  Rnb);
    make_rot(strong + 6,  Ra1);
    make_rot(strong + 9,  Ra1p);
    make_rot(strong + 12, Rnbp);
    make_rot(strong + 15, Ra2);
    make_rot(update + 0,  U0);
    make_rot(update + 3,  U1);

    float2 T[4], M[4];
    // FB1[b3*2+b2] = Ra1 * RY1^{b3} * RX0^{b2}
    for (int b3 = 0; b3 < 2; b3++)
        for (int b2 = 0; b2 < 2; b2++) {
            cm2(b3 ? RY1 : I2, b2 ? RX0 : I2, T);
            cm2(Ra1, T, M);
            write_mat(b3 * 2 + b2, M);
        }
    // FB0[b3*2+b2] = Ra2 * RY3^{b3} * RZ2^{b2}
    for (int b3 = 0; b3 < 2; b3++)
        for (int b2 = 0; b2 < 2; b2++) {
            cm2(b3 ? RY3 : I2, b2 ? RZ2 : I2, T);
            cm2(Ra2, T, M);
            write_mat(4 + b3 * 2 + b2, M);
        }
    write_mat(8,  Re);
    write_mat(9,  Rnb);
    write_mat(10, Ra1p);
    write_mat(11, Rnbp);
    // Q = H * A  (so observable becomes Z with sign = parity of bits 3,1)
    const float rh = 0.70710678118654752f;
    float2 H2[4];
    H2[0] = make_float2(rh, 0); H2[1] = make_float2(rh, 0);
    H2[2] = make_float2(rh, 0); H2[3] = make_float2(-rh, 0);
    cm2(H2, U0, M); write_mat(12, M);
    cm2(H2, U1, M); write_mat(13, M);
}

// ---------------- fused node+edge MLP (+ prep + W columns) ----------------
template <int NI, bool IS_NODE>
__device__ __forceinline__ void mlp_row(const float* __restrict__ inp, int r,
                                        const float* sW1, const float* sb1,
                                        const float* sW2, const float* sb2) {
    float in[NI];
#pragma unroll
    for (int i = 0; i < NI; i++) in[i] = inp[r * NI + i];
    float o0 = sb2[0], o1 = sb2[1];
#pragma unroll 4
    for (int h = 0; h < 128; h++) {
        float a = sb1[h];
#pragma unroll
        for (int i = 0; i < NI; i++) a = fmaf(in[i], sW1[i * 128 + h], a);
        a = a > 0.f ? a : 0.01f * a;
        o0 = fmaf(a, sW2[2 * h], o0);
        o1 = fmaf(a, sW2[2 * h + 1], o1);
    }
    float t0 = tanhf(o0) * PI_F;
    float t1 = tanhf(o1) * PI_F;
    float sy, cy, sz, cz;
    sincosf(0.5f * t0, &sy, &cy);
    sincosf(0.5f * t1, &sz, &cz);
    float4 amps = make_float4(cy * cz, -cy * sz, sy * cz, sy * sz);
    if (IS_NODE) {
        g_x[2 * r] = t0; g_x[2 * r + 1] = t1;
        g_x4[r] = amps;
    } else {
        g_e4[r] = amps;
    }
}

__global__ void __launch_bounds__(256) mlp_fused_kernel(
    const float* __restrict__ node_feat,
    const float* __restrict__ Wn1, const float* __restrict__ bn1,
    const float* __restrict__ Wn2, const float* __restrict__ bn2,
    const float* __restrict__ edge_attr,
    const float* __restrict__ We1, const float* __restrict__ be1,
    const float* __restrict__ We2, const float* __restrict__ be2,
    const float* __restrict__ strong, const float* __restrict__ inits,
    const float* __restrict__ update) {
    __shared__ float sW1[8 * 128];
    __shared__ float sb1[128];
    __shared__ float sW2[256];
    __shared__ float sb2[2];
    int b = blockIdx.x, tid = threadIdx.x;
    bool isNode = (b < 16);
    const float* W1 = isNode ? Wn1 : We1;
    const float* b1 = isNode ? bn1 : be1;
    const float* W2 = isNode ? Wn2 : We2;
    const float* b2 = isNode ? bn2 : be2;
    int nv4 = (isNode ? 8 : 4) * 32;
    for (int k = tid; k < nv4; k += 256)
        ((float4*)sW1)[k] = ((const float4*)W1)[k];
    if (tid < 128) sb1[tid] = b1[tid];
    sW2[tid] = W2[tid];
    if (tid < 2) sb2[tid] = b2[tid];

    if (b == 0) {
        if (tid < NUM_GRAPHS) {
            g_gsum[2 * tid] = 0.f; g_gsum[2 * tid + 1] = 0.f; g_gcnt[tid] = 0.f;
        }
        if (tid == 33) g_done = 0;
        if (tid == 32) prep_gates(strong, inits, update);
    }
    __syncthreads();

    // W columns: new-iter0 applied to basis states e_{8a+4b}, k = 2a+b
    if (b == 0 && tid >= 64 && tid < 68) {
        int k = tid - 64;
        ull v[16];
#pragma unroll
        for (int r = 0; r < 16; r++) v[r] = 0ull;
        v[((k >> 1) << 3) | ((k & 1) << 2)] = pk(1.f, 0.f);
        iter_regs2(v, g_gx);
#pragma unroll
        for (int r = 0; r < 16; r++) {
            g_wx[2 * (k * 16 + r)]     = v[r];
            g_wx[2 * (k * 16 + r) + 1] = jsw(v[r]);
        }
    }

    if (isNode)
        mlp_row<8, true>(node_feat, b * 256 + tid, sW1, sb1, sW2, sb2);
    else
        mlp_row<4, false>(edge_attr, (b - 16) * 256 + tid, sW1, sb1, sW2, sb2);
}

// ================= PQC kernel =================
__device__ __forceinline__ float2 pick(float4 a, int bit) {
    return bit ? make_float2(a.z, a.w) : make_float2(a.x, a.y);
}

__global__ void __launch_bounds__(256, 3) pqc_kernel(
    const int* __restrict__ subgraphs, const int* __restrict__ edge_ids,
    const int* __restrict__ batch,
    const float* __restrict__ Wu1, const float* __restrict__ bu1,
    const float* __restrict__ Wu2, const float* __restrict__ bu2,
    const float* __restrict__ Wh1, const float* __restrict__ bh1,
    const float* __restrict__ Wh2, const float* __restrict__ bh2,
    float* __restrict__ out) {
    __shared__ ull sGx[112];
    __shared__ ull sWx[128];
    __shared__ float sW1[384];
    __shared__ float sb1[128];
    __shared__ float sW2[256];
    __shared__ float sb2[2];
    __shared__ float sAcc[NUM_GRAPHS * 3];
    __shared__ int sLast;
    int tid = threadIdx.x;
    if (tid < 112) sGx[tid] = g_gx[tid];
    if (tid >= 112 && tid < 240) sWx[tid - 112] = g_wx[tid - 112];
    for (int k = tid; k < 384; k += 256) sW1[k] = Wu1[k];
    if (tid < 128) sb1[tid] = bu1[tid];
    sW2[tid] = Wu2[tid];
    if (tid < 2) sb2[tid] = bu2[tid];
    if (tid < NUM_GRAPHS * 3) sAcc[tid] = 0.f;
    __syncthreads();

    int lane = tid & 31;
    int s = blockIdx.x * 8 + (tid >> 5);

    // lane bits: L4(16)=w1, L3(8)=w2, L2(4)=w3(n0), L1(2)=w5(n2), L0(1)=w6(n3)
    // reg bits:  R3=w0(e0) (iter0 active e), R2=w4(n1), R1=a1, R0=a2
    int e0 = edge_ids[3 * s], e1 = edge_ids[3 * s + 1], e2 = edge_ids[3 * s + 2];
    int n0 = subgraphs[4 * s], n1 = subgraphs[4 * s + 1],
        n2 = subgraphs[4 * s + 2], n3 = subgraphs[4 * s + 3];

    float x0c = g_x[2 * n0], x1c = g_x[2 * n0 + 1];

    float2 lf = pick(g_e4[e1], (lane >> 4) & 1);
    lf = cmul(lf, pick(g_e4[e2], (lane >> 3) & 1));
    lf = cmul(lf, pick(g_x4[n0], (lane >> 2) & 1));
    lf = cmul(lf, pick(g_x4[n2], (lane >> 1) & 1));
    lf = cmul(lf, pick(g_x4[n3], lane & 1));
    float4 aw0 = g_e4[e0];
    float4 aw4 = g_x4[n1];

    float2 c0 = cmul(lf, cmul(pick(aw0, 0), pick(aw4, 0)));
    float2 c1 = cmul(lf, cmul(pick(aw0, 0), pick(aw4, 1)));
    float2 c2 = cmul(lf, cmul(pick(aw0, 1), pick(aw4, 0)));
    float2 c3 = cmul(lf, cmul(pick(aw0, 1), pick(aw4, 1)));
    ull c0x = pk(c0.x, c0.x), c0y = pk(c0.y, c0.y);
    ull c1x = pk(c1.x, c1.x), c1y = pk(c1.y, c1.y);
    ull c2x = pk(c2.x, c2.x), c2y = pk(c2.y, c2.y);
    ull c3x = pk(c3.x, c3.x), c3y = pk(c3.y, c3.y);

    // post-iter0 state: v = sum_k c_k * W_k  (c*W = c.x*W + c.y*(iW))
    ull v[16];
#pragma unroll
    for (int r = 0; r < 16; r++)
        v[r] = fma2(c0x, sWx[2 * r],
               fma2(c0y, sWx[2 * r + 1],
               fma2(c1x, sWx[2 * (16 + r)],
               fma2(c1y, sWx[2 * (16 + r) + 1],
               fma2(c2x, sWx[2 * (32 + r)],
               fma2(c2y, sWx[2 * (32 + r) + 1],
               fma2(c3x, sWx[2 * (48 + r)],
               mul2(c3y, sWx[2 * (48 + r) + 1]))))))));

    // retarget: R3: w0<->w1(L4), R2: w4<->w5(L1)
    swap_reg_lane<3>(v, lane, 16);
    swap_reg_lane<2>(v, lane, 2);
    iter_regs2(v, sGx);                  // iteration 1: e=w1, nb=w5
    swap_reg_lane<3>(v, lane, 8);
    swap_reg_lane<2>(v, lane, 1);
    iter_regs2(v, sGx);                  // iteration 2: e=w2, nb=w6
    swap_reg_lane<3>(v, lane, 4);        // R3 <- w3

    // final: Q3 on R3, Q1 on R1 (observable diagonalized; rot on a2 drops out)
    ap_reg2<3>(v, sGx + 96);
    ap_reg2<1>(v, sGx + 104);

    // aggr = sum_r s_r |w_r|^2,  s_r = +1 if bit3==bit1 else -1
    float part = 0.f;
#pragma unroll
    for (int r = 0; r < 16; r++) {
        float x, y; upk(v[r], x, y);
        float t = fmaf(x, x, y * y);
        part = (((r >> 3) ^ (r >> 1)) & 1) ? part - t : part + t;
    }
#pragma unroll
    for (int o = 16; o; o >>= 1) part += __shfl_xor_sync(0xffffffffu, part, o);
    float aggr = part;

    // fused update MLP: in = [x0c, x1c, aggr], 4 hidden units per lane
    float o0 = 0.f, o1 = 0.f;
#pragma unroll
    for (int k = 0; k < 4; k++) {
        int h = lane + 32 * k;
        float a = fmaf(x0c, sW1[h],
                  fmaf(x1c, sW1[128 + h],
                  fmaf(aggr, sW1[256 + h], sb1[h])));
        a = a > 0.f ? a : 0.01f * a;
        o0 = fmaf(a, sW2[2 * h], o0);
        o1 = fmaf(a, sW2[2 * h + 1], o1);
    }
#pragma unroll
    for (int o = 16; o; o >>= 1) {
        o0 += __shfl_xor_sync(0xffffffffu, o0, o);
        o1 += __shfl_xor_sync(0xffffffffu, o1, o);
    }
    if (lane == 0) {
        o0 += sb2[0]; o1 += sb2[1];
        int gu = batch[n0];
        int gx = batch[s];
        atomicAdd(&sAcc[3 * gu + 0], o0);
        atomicAdd(&sAcc[3 * gu + 1], o1);
        atomicAdd(&sAcc[3 * gx + 0], g_x[2 * s]);
        atomicAdd(&sAcc[3 * gx + 1], g_x[2 * s + 1]);
        atomicAdd(&sAcc[3 * gx + 2], 1.f);
    }
    __syncthreads();

    if (tid < NUM_GRAPHS) {
        atomicAdd(&g_gsum[2 * tid],     sAcc[3 * tid + 0]);
        atomicAdd(&g_gsum[2 * tid + 1], sAcc[3 * tid + 1]);
        atomicAdd(&g_gcnt[tid],         sAcc[3 * tid + 2]);
        __threadfence();
    }
    __syncthreads();
    if (tid == 0) {
        int old = atomicAdd(&g_done, 1);
        sLast = (old == PQC_BLOCKS - 1);
        __threadfence();
    }
    __syncthreads();

    if (sLast && tid < NUM_GRAPHS) {
        int g = tid;
        float cnt = __ldcg(&g_gcnt[g]);
        float g0 = __ldcg(&g_gsum[2 * g]) / cnt;
        float g1 = __ldcg(&g_gsum[2 * g + 1]) / cnt;
        float h0 = g0 * Wh1[0] + g1 * Wh1[2] + bh1[0];
        float h1 = g0 * Wh1[1] + g1 * Wh1[3] + bh1[1];
        h0 = h0 > 0.f ? h0 : 0.01f * h0;
        h1 = h1 > 0.f ? h1 : 0.01f * h1;
        out[2 * g]     = h0 * Wh2[0] + h1 * Wh2[2] + bh2[0];
        out[2 * g + 1] = h0 * Wh2[1] + h1 * Wh2[3] + bh2[1];
    }
}

// ---------------- launch ----------------
extern "C" void kernel_launch(void* const* d_in, const int* in_sizes, int n_in,
                              void* d_out, int out_size) {
    const float* node_feat = (const float*)d_in[0];
    const float* edge_attr = (const float*)d_in[1];
    const float* Wn1 = (const float*)d_in[2];
    const float* bn1 = (const float*)d_in[3];
    const float* Wn2 = (const float*)d_in[4];
    const float* bn2 = (const float*)d_in[5];
    const float* We1 = (const float*)d_in[6];
    const float* be1 = (const float*)d_in[7];
    const float* We2 = (const float*)d_in[8];
    const float* be2 = (const float*)d_in[9];
    const float* strong = (const float*)d_in[10];
    const float* inits  = (const float*)d_in[11];
    const float* update = (const float*)d_in[12];
    const float* Wu1 = (const float*)d_in[13];
    const float* bu1 = (const float*)d_in[14];
    const float* Wu2 = (const float*)d_in[15];
    const float* bu2 = (const float*)d_in[16];
    const float* Wh1 = (const float*)d_in[17];
    const float* bh1 = (const float*)d_in[18];
    const float* Wh2 = (const float*)d_in[19];
    const float* bh2 = (const float*)d_in[20];
    const int* subgraphs = (const int*)d_in[21];
    const int* edge_ids  = (const int*)d_in[22];
    const int* batch     = (const int*)d_in[23];
    float* out = (float*)d_out;

    mlp_fused_kernel<<<64, 256>>>(node_feat, Wn1, bn1, Wn2, bn2,
                                  edge_attr, We1, be1, We2, be2,
                                  strong, inits, update);
    pqc_kernel<<<PQC_BLOCKS, 256>>>(subgraphs, edge_ids, batch,
                                    Wu1, bu1, Wu2, bu2,
                                    Wh1, bh1, Wh2, bh2, out);
}

// round 7
// speedup vs baseline: 1.3683x; 1.3683x over previous
#include <cuda_runtime.h>
#include <math.h>

#define PI_F 3.14159265358979323846f
#define N_NODES 4096
#define N_EDGES 12288
#define NUM_GRAPHS 16
#define PQC_BLOCKS 512

// ---------------- device scratch ----------------
__device__ float  g_x[N_NODES * 2];     // node angles (update-MLP input & segment sum)
__device__ float4 g_x4[N_NODES];        // node wire amplitudes
__device__ float4 g_e4[N_EDGES];        // edge wire amplitudes
// gate table: [0..15] FB1 (4 branch matrices for a1), [16..31] FB0 (a2),
// [32..35] Re, [36..39] Rnb, [40..43] Ra1p, [44..47] Rnbp, [48..51] Q3, [52..55] Q1
__device__ float2 g_gates[56];
__device__ float2 g_w[64];              // 4 precomputed iter0 output columns (16 each)
__device__ float  g_gsum[NUM_GRAPHS * 2];
__device__ float  g_gcnt[NUM_GRAPHS];
__device__ int    g_done;

// ---------------- complex helpers ----------------
__device__ __forceinline__ float2 cmul(float2 a, float2 b) {
    return make_float2(fmaf(a.x, b.x, -(a.y * b.y)), fmaf(a.x, b.y, a.y * b.x));
}
__device__ __forceinline__ float2 cfma(float2 a, float2 b, float2 c) {   // a*b + c
    return make_float2(fmaf(a.x, b.x, fmaf(-a.y, b.y, c.x)),
                       fmaf(a.x, b.y, fmaf( a.y, b.x, c.y)));
}
__device__ __forceinline__ float2 cadd(float2 a, float2 b) {
    return make_float2(a.x + b.x, a.y + b.y);
}

// ================= PQC register-gate primitives (scalar float2) =================
// Register bits: R0=a2, R1=a1, R2=nb, R3=e
template <int J>
__device__ __forceinline__ void ap_reg(float2* v, const float2* U) {
    float2 u0 = U[0], u1 = U[1], u2 = U[2], u3 = U[3];
#pragma unroll
    for (int r = 0; r < 16; r++) {
        if ((r >> J) & 1) continue;
        int r2 = r | (1 << J);
        float2 a = v[r], b = v[r2];
        v[r]  = cfma(u1, b, cmul(u0, a));
        v[r2] = cfma(u3, b, cmul(u2, a));
    }
}
// 1q gate on register bit J, matrix selected by bits (3,2)
template <int J>
__device__ __forceinline__ void ap_branch(float2* v, const float2* FB) {
#pragma unroll
    for (int r = 0; r < 16; r++) {
        if ((r >> J) & 1) continue;
        const float2* U = FB + 4 * ((r >> 2) & 3);
        int r2 = r | (1 << J);
        float2 a = v[r], b = v[r2];
        v[r]  = cfma(U[1], b, cmul(U[0], a));
        v[r2] = cfma(U[3], b, cmul(U[2], a));
    }
}
template <int C, int T>
__device__ __forceinline__ void cnot_rr(float2* v) {
#pragma unroll
    for (int r = 0; r < 16; r++) {
        if (!((r >> C) & 1) || ((r >> T) & 1)) continue;
        int r2 = r | (1 << T);
        float2 t = v[r]; v[r] = v[r2]; v[r2] = t;
    }
}
template <int J>
__device__ __forceinline__ void swap_reg_lane(float2* v, int lane, int mask) {
    bool b = lane & mask;
#pragma unroll
    for (int r = 0; r < 16; r++) {
        if ((r >> J) & 1) continue;
        int r2 = r | (1 << J);
        float2 send = b ? v[r] : v[r2];
        float2 recv;
        recv.x = __shfl_xor_sync(0xffffffffu, send.x, mask);
        recv.y = __shfl_xor_sync(0xffffffffu, send.y, mask);
        if (b) v[r] = recv; else v[r2] = recv;
    }
}

// one ctrl+sel+sel iteration (branch-fused controlled gates)
__device__ __forceinline__ void iter_regs(float2* v, const float2* sG) {
    ap_branch<1>(v, sG);          // FB1 = Ra1 * CRY(e->a1) * CRX(nb->a1)
    ap_branch<0>(v, sG + 16);     // FB0 = Ra2 * CRY(e->a2) * CRZ(nb->a2)
    ap_reg<3>(v, sG + 32);        // Re
    ap_reg<2>(v, sG + 36);        // Rnb
    cnot_rr<3, 2>(v);
    cnot_rr<2, 1>(v);
    cnot_rr<1, 3>(v);
    ap_reg<1>(v, sG + 40);        // Ra1'
    ap_reg<2>(v, sG + 44);        // Rnb'
    cnot_rr<1, 2>(v);
    cnot_rr<2, 0>(v);
    cnot_rr<0, 1>(v);
}

// ---------------- gate precompute ----------------
__device__ void make_rot(const float* w, float2* m) {
    float phi = w[0], th = w[1], om = w[2];
    float c, s; sincosf(th * 0.5f, &s, &c);
    float sa, ca, sb, cb;
    sincosf((phi + om) * 0.5f, &sa, &ca);
    sincosf((phi - om) * 0.5f, &sb, &cb);
    m[0] = make_float2(c * ca, -c * sa);
    m[1] = make_float2(-s * cb, -s * sb);
    m[2] = make_float2(s * cb, -s * sb);
    m[3] = make_float2(c * ca, c * sa);
}
__device__ void cm2(const float2* A, const float2* B, float2* C) {
    C[0] = cadd(cmul(A[0], B[0]), cmul(A[1], B[2]));
    C[1] = cadd(cmul(A[0], B[1]), cmul(A[1], B[3]));
    C[2] = cadd(cmul(A[2], B[0]), cmul(A[3], B[2]));
    C[3] = cadd(cmul(A[2], B[1]), cmul(A[3], B[3]));
}

__device__ void prep_gates(const float* strong, const float* inits, const float* update) {
    float c, s;
    float2 RX0[4], RY1[4], RZ2[4], RY3[4], I2[4];
    I2[0] = make_float2(1, 0); I2[1] = make_float2(0, 0);
    I2[2] = make_float2(0, 0); I2[3] = make_float2(1, 0);
    sincosf(inits[0] * 0.5f, &s, &c);
    RX0[0] = make_float2(c, 0); RX0[1] = make_float2(0, -s);
    RX0[2] = make_float2(0, -s); RX0[3] = make_float2(c, 0);
    sincosf(inits[1] * 0.5f, &s, &c);
    RY1[0] = make_float2(c, 0); RY1[1] = make_float2(-s, 0);
    RY1[2] = make_float2(s, 0); RY1[3] = make_float2(c, 0);
    sincosf(inits[2] * 0.5f, &s, &c);
    RZ2[0] = make_float2(c, -s); RZ2[1] = make_float2(0, 0);
    RZ2[2] = make_float2(0, 0);  RZ2[3] = make_float2(c, s);
    sincosf(inits[3] * 0.5f, &s, &c);
    RY3[0] = make_float2(c, 0); RY3[1] = make_float2(-s, 0);
    RY3[2] = make_float2(s, 0); RY3[3] = make_float2(c, 0);

    float2 Re[4], Rnb[4], Ra1[4], Ra1p[4], Rnbp[4], Ra2[4], U0[4], U1[4];
    make_rot(strong + 0,  Re);
    make_rot(strong + 3,  Rnb);
    make_rot(strong + 6,  Ra1);
    make_rot(strong + 9,  Ra1p);
    make_rot(strong + 12, Rnbp);
    make_rot(strong + 15, Ra2);
    make_rot(update + 0,  U0);
    make_rot(update + 3,  U1);

    float2 T[4], M[4];
    // FB1[b3*2+b2] = Ra1 * RY1^{b3} * RX0^{b2}   (b3 = e bit, b2 = nb bit)
    for (int b3 = 0; b3 < 2; b3++)
        for (int b2 = 0; b2 < 2; b2++) {
            cm2(b3 ? RY1 : I2, b2 ? RX0 : I2, T);
            cm2(Ra1, T, M);
            for (int k = 0; k < 4; k++) g_gates[(b3 * 2 + b2) * 4 + k] = M[k];
        }
    // FB0[b3*2+b2] = Ra2 * RY3^{b3} * RZ2^{b2}
    for (int b3 = 0; b3 < 2; b3++)
        for (int b2 = 0; b2 < 2; b2++) {
            cm2(b3 ? RY3 : I2, b2 ? RZ2 : I2, T);
            cm2(Ra2, T, M);
            for (int k = 0; k < 4; k++) g_gates[16 + (b3 * 2 + b2) * 4 + k] = M[k];
        }
    for (int k = 0; k < 4; k++) g_gates[32 + k] = Re[k];
    for (int k = 0; k < 4; k++) g_gates[36 + k] = Rnb[k];
    for (int k = 0; k < 4; k++) g_gates[40 + k] = Ra1p[k];
    for (int k = 0; k < 4; k++) g_gates[44 + k] = Rnbp[k];
    // Q = H * U (observable diagonalization)
    const float rh = 0.70710678118654752f;
    float2 H2[4];
    H2[0] = make_float2(rh, 0); H2[1] = make_float2(rh, 0);
    H2[2] = make_float2(rh, 0); H2[3] = make_float2(-rh, 0);
    cm2(H2, U0, M); for (int k = 0; k < 4; k++) g_gates[48 + k] = M[k];
    cm2(H2, U1, M); for (int k = 0; k < 4; k++) g_gates[52 + k] = M[k];
}

// ---------------- fused node+edge MLP (+ prep + W columns) ----------------
template <int NI, bool IS_NODE>
__device__ __forceinline__ void mlp_row(const float* __restrict__ inp, int r,
                                        const float* sW1, const float* sb1,
                                        const float* sW2, const float* sb2) {
    float in[NI];
#pragma unroll
    for (int i = 0; i < NI; i++) in[i] = inp[r * NI + i];
    float o0 = sb2[0], o1 = sb2[1];
#pragma unroll 4
    for (int h = 0; h < 128; h++) {
        float a = sb1[h];
#pragma unroll
        for (int i = 0; i < NI; i++) a = fmaf(in[i], sW1[i * 128 + h], a);
        a = a > 0.f ? a : 0.01f * a;
        o0 = fmaf(a, sW2[2 * h], o0);
        o1 = fmaf(a, sW2[2 * h + 1], o1);
    }
    float t0 = tanhf(o0) * PI_F;   // ry
    float t1 = tanhf(o1) * PI_F;   // rz
    float sy, cy, sz, cz;
    sincosf(0.5f * t0, &sy, &cy);
    sincosf(0.5f * t1, &sz, &cz);
    float4 amps = make_float4(cy * cz, -cy * sz, sy * cz, sy * sz);
    if (IS_NODE) {
        g_x[2 * r] = t0; g_x[2 * r + 1] = t1;
        g_x4[r] = amps;
    } else {
        g_e4[r] = amps;
    }
}

__global__ void __launch_bounds__(128) mlp_fused_kernel(
    const float* __restrict__ node_feat,
    const float* __restrict__ Wn1, const float* __restrict__ bn1,
    const float* __restrict__ Wn2, const float* __restrict__ bn2,
    const float* __restrict__ edge_attr,
    const float* __restrict__ We1, const float* __restrict__ be1,
    const float* __restrict__ We2, const float* __restrict__ be2,
    const float* __restrict__ strong, const float* __restrict__ inits,
    const float* __restrict__ update) {
    __shared__ float sW1[8 * 128];
    __shared__ float sb1[128];
    __shared__ float sW2[256];
    __shared__ float sb2[2];
    int b = blockIdx.x, tid = threadIdx.x;
    bool isNode = (b < 32);
    const float* W1 = isNode ? Wn1 : We1;
    const float* b1 = isNode ? bn1 : be1;
    const float* W2 = isNode ? Wn2 : We2;
    const float* b2 = isNode ? bn2 : be2;
    int ni = isNode ? 8 : 4;
    for (int k = tid; k < ni * 128; k += 128) sW1[k] = W1[k];
    sb1[tid] = b1[tid];
    sW2[tid] = W2[tid]; sW2[128 + tid] = W2[128 + tid];
    if (tid < 2) sb2[tid] = b2[tid];

    if (b == 0) {
        if (tid < NUM_GRAPHS) {
            g_gsum[2 * tid] = 0.f; g_gsum[2 * tid + 1] = 0.f; g_gcnt[tid] = 0.f;
        }
        if (tid == 33) g_done = 0;
        if (tid == 32) prep_gates(strong, inits, update);
    }
    __syncthreads();

    // W columns: iter0 applied to basis states e_{8a+4b}, k = 2a+b
    if (b == 0 && tid >= 64 && tid < 68) {
        int k = tid - 64;
        float2 v[16];
#pragma unroll
        for (int r = 0; r < 16; r++) v[r] = make_float2(0.f, 0.f);
        v[((k >> 1) << 3) | ((k & 1) << 2)] = make_float2(1.f, 0.f);
        iter_regs(v, g_gates);
#pragma unroll
        for (int r = 0; r < 16; r++) g_w[k * 16 + r] = v[r];
    }

    if (isNode)
        mlp_row<8, true>(node_feat, b * 128 + tid, sW1, sb1, sW2, sb2);
    else
        mlp_row<4, false>(edge_attr, (b - 32) * 128 + tid, sW1, sb1, sW2, sb2);
}

// ================= PQC kernel =================
__device__ __forceinline__ float2 pick(float4 a, int bit) {
    return bit ? make_float2(a.z, a.w) : make_float2(a.x, a.y);
}

__global__ void __launch_bounds__(256) pqc_kernel(
    const int* __restrict__ subgraphs, const int* __restrict__ edge_ids,
    const int* __restrict__ batch,
    const float* __restrict__ Wu1, const float* __restrict__ bu1,
    const float* __restrict__ Wu2, const float* __restrict__ bu2,
    const float* __restrict__ Wh1, const float* __restrict__ bh1,
    const float* __restrict__ Wh2, const float* __restrict__ bh2,
    float* __restrict__ out) {
    __shared__ float2 sG[56];
    __shared__ float2 sWC[64];
    __shared__ float sW1[384];
    __shared__ float sb1[128];
    __shared__ float sW2[256];
    __shared__ float sb2[2];
    __shared__ float sAcc[NUM_GRAPHS * 3];
    __shared__ int sLast;
    int tid = threadIdx.x;
    if (tid < 56) sG[tid] = g_gates[tid];
    if (tid >= 64 && tid < 128) sWC[tid - 64] = g_w[tid - 64];
    for (int k = tid; k < 384; k += 256) sW1[k] = Wu1[k];
    if (tid < 128) sb1[tid] = bu1[tid];
    sW2[tid] = Wu2[tid];
    if (tid < 2) sb2[tid] = bu2[tid];
    if (tid < NUM_GRAPHS * 3) sAcc[tid] = 0.f;
    __syncthreads();

    int lane = tid & 31;
    int s = blockIdx.x * 8 + (tid >> 5);

    // lane bits: L4(16)=w1, L3(8)=w2, L2(4)=w3(n0), L1(2)=w5(n2), L0(1)=w6(n3)
    // reg bits:  R3=w0(e0), R2=w4(n1), R1=a1, R0=a2
    int e0 = edge_ids[3 * s], e1 = edge_ids[3 * s + 1], e2 = edge_ids[3 * s + 2];
    int n0 = subgraphs[4 * s], n1 = subgraphs[4 * s + 1],
        n2 = subgraphs[4 * s + 2], n3 = subgraphs[4 * s + 3];

    float x0c = g_x[2 * n0], x1c = g_x[2 * n0 + 1];

    float2 lf = pick(g_e4[e1], (lane >> 4) & 1);
    lf = cmul(lf, pick(g_e4[e2], (lane >> 3) & 1));
    lf = cmul(lf, pick(g_x4[n0], (lane >> 2) & 1));
    lf = cmul(lf, pick(g_x4[n2], (lane >> 1) & 1));
    lf = cmul(lf, pick(g_x4[n3], lane & 1));
    float4 aw0 = g_e4[e0];
    float4 aw4 = g_x4[n1];

    float2 c0 = cmul(lf, cmul(pick(aw0, 0), pick(aw4, 0)));
    float2 c1 = cmul(lf, cmul(pick(aw0, 0), pick(aw4, 1)));
    float2 c2 = cmul(lf, cmul(pick(aw0, 1), pick(aw4, 0)));
    float2 c3 = cmul(lf, cmul(pick(aw0, 1), pick(aw4, 1)));

    // post-iter0 state via precomputed columns
    float2 v[16];
#pragma unroll
    for (int r = 0; r < 16; r++)
        v[r] = cfma(c3, sWC[48 + r],
               cfma(c2, sWC[32 + r],
               cfma(c1, sWC[16 + r],
               cmul(c0, sWC[r]))));

    // retarget: R3: w0<->w1(L4), R2: w4<->w5(L1)
    swap_reg_lane<3>(v, lane, 16);
    swap_reg_lane<2>(v, lane, 2);
    iter_regs(v, sG);                     // iteration 1: e=w1, nb=w5
    swap_reg_lane<3>(v, lane, 8);
    swap_reg_lane<2>(v, lane, 1);
    iter_regs(v, sG);                     // iteration 2: e=w2, nb=w6
    swap_reg_lane<3>(v, lane, 4);         // R3 <- w3

    // final: Q3 on R3, Q1 on R1 (observable = Z3*Z1 after conjugation)
    ap_reg<3>(v, sG + 48);
    ap_reg<1>(v, sG + 52);

    // aggr = sum_r s_r |v_r|^2, s_r = +1 if bit3==bit1 else -1
    float part = 0.f;
#pragma unroll
    for (int r = 0; r < 16; r++) {
        float t = fmaf(v[r].x, v[r].x, v[r].y * v[r].y);
        part = (((r >> 3) ^ (r >> 1)) & 1) ? part - t : part + t;
    }
#pragma unroll
    for (int o = 16; o; o >>= 1) part += __shfl_xor_sync(0xffffffffu, part, o);
    float aggr = part;

    // fused update MLP: in = [x0c, x1c, aggr], 4 hidden units per lane
    float o0 = 0.f, o1 = 0.f;
#pragma unroll
    for (int k = 0; k < 4; k++) {
        int h = lane + 32 * k;
        float a = fmaf(x0c, sW1[h],
                  fmaf(x1c, sW1[128 + h],
                  fmaf(aggr, sW1[256 + h], sb1[h])));
        a = a > 0.f ? a : 0.01f * a;
        o0 = fmaf(a, sW2[2 * h], o0);
        o1 = fmaf(a, sW2[2 * h + 1], o1);
    }
#pragma unroll
    for (int o = 16; o; o >>= 1) {
        o0 += __shfl_xor_sync(0xffffffffu, o0, o);
        o1 += __shfl_xor_sync(0xffffffffu, o1, o);
    }
    if (lane == 0) {
        o0 += sb2[0]; o1 += sb2[1];
        int gu = batch[n0];
        int gx = batch[s];
        atomicAdd(&sAcc[3 * gu + 0], o0);
        atomicAdd(&sAcc[3 * gu + 1], o1);
        atomicAdd(&sAcc[3 * gx + 0], g_x[2 * s]);
        atomicAdd(&sAcc[3 * gx + 1], g_x[2 * s + 1]);
        atomicAdd(&sAcc[3 * gx + 2], 1.f);
    }
    __syncthreads();

    if (tid < NUM_GRAPHS) {
        atomicAdd(&g_gsum[2 * tid],     sAcc[3 * tid + 0]);
        atomicAdd(&g_gsum[2 * tid + 1], sAcc[3 * tid + 1]);
        atomicAdd(&g_gcnt[tid],         sAcc[3 * tid + 2]);
        __threadfence();
    }
    __syncthreads();
    if (tid == 0) {
        int old = atomicAdd(&g_done, 1);
        sLast = (old == PQC_BLOCKS - 1);
        __threadfence();
    }
    __syncthreads();

    if (sLast && tid < NUM_GRAPHS) {
        int g = tid;
        float cnt = __ldcg(&g_gcnt[g]);
        float g0 = __ldcg(&g_gsum[2 * g]) / cnt;
        float g1 = __ldcg(&g_gsum[2 * g + 1]) / cnt;
        float h0 = g0 * Wh1[0] + g1 * Wh1[2] + bh1[0];
        float h1 = g0 * Wh1[1] + g1 * Wh1[3] + bh1[1];
        h0 = h0 > 0.f ? h0 : 0.01f * h0;
        h1 = h1 > 0.f ? h1 : 0.01f * h1;
        out[2 * g]     = h0 * Wh2[0] + h1 * Wh2[2] + bh2[0];
        out[2 * g + 1] = h0 * Wh2[1] + h1 * Wh2[3] + bh2[1];
    }
}

// ---------------- launch ----------------
extern "C" void kernel_launch(void* const* d_in, const int* in_sizes, int n_in,
                              void* d_out, int out_size) {
    const float* node_feat = (const float*)d_in[0];
    const float* edge_attr = (const float*)d_in[1];
    const float* Wn1 = (const float*)d_in[2];
    const float* bn1 = (const float*)d_in[3];
    const float* Wn2 = (const float*)d_in[4];
    const float* bn2 = (const float*)d_in[5];
    const float* We1 = (const float*)d_in[6];
    const float* be1 = (const float*)d_in[7];
    const float* We2 = (const float*)d_in[8];
    const float* be2 = (const float*)d_in[9];
    const float* strong = (const float*)d_in[10];
    const float* inits  = (const float*)d_in[11];
    const float* update = (const float*)d_in[12];
    const float* Wu1 = (const float*)d_in[13];
    const float* bu1 = (const float*)d_in[14];
    const float* Wu2 = (const float*)d_in[15];
    const float* bu2 = (const float*)d_in[16];
    const float* Wh1 = (const float*)d_in[17];
    const float* bh1 = (const float*)d_in[18];
    const float* Wh2 = (const float*)d_in[19];
    const float* bh2 = (const float*)d_in[20];
    const int* subgraphs = (const int*)d_in[21];
    const int* edge_ids  = (const int*)d_in[22];
    const int* batch     = (const int*)d_in[23];
    float* out = (float*)d_out;

    mlp_fused_kernel<<<128, 128>>>(node_feat, Wn1, bn1, Wn2, bn2,
                                   edge_attr, We1, be1, We2, be2,
                                   strong, inits, update);
    pqc_kernel<<<PQC_BLOCKS, 256>>>(subgraphs, edge_ids, batch,
                                    Wu1, bu1, Wu2, bu2,
                                    Wh1, bh1, Wh2, bh2, out);
}